// round 16
// baseline (speedup 1.0000x reference)
#include <cuda_runtime.h>

#define B_ 4
#define C_ 64
#define N_ 8192
#define K_ 32
#define R2_ 0.04f
#define BN_EPS_ 1e-5f
#define NC 5
#define NCELL (NC * NC * NC)
#define INFB 0x7f800000u

typedef unsigned long long ull;

#define FMA2ACC(acc, a, bb) asm("fma.rn.f32x2 %0, %1, %2, %0;" : "+l"(acc) : "l"(a), "l"(bb))

__device__ __forceinline__ ull pack2(float lo, float hi) {
    ull r; asm("mov.b64 %0, {%1, %2};" : "=l"(r) : "f"(lo), "f"(hi)); return r;
}
__device__ __forceinline__ void unpack2(ull v, float& lo, float& hi) {
    asm("mov.b64 {%0, %1}, %2;" : "=f"(lo), "=f"(hi) : "l"(v));
}
__device__ __forceinline__ int cell_clamp(float v) {
    int c = (int)(v * 5.0f);
    return min(NC - 1, max(0, c));
}

// Scratch (static __device__ arrays — no allocation)
__device__ float  g_F[B_ * N_ * C_];      // F[b][n][d] = fea row . W_fea[d] * scale
__device__ int    g_gidx[B_ * N_ * K_];   // final (masked) neighbor indices
__device__ __align__(16) ull g_WsT2[32 * 64];  // packed (w[2c],w[2c+1]) per d
__device__ float  g_Wc[3 * 64];           // coord weights * scale
__device__ float  g_bias[64];             // BN-folded bias
// grid structures
__device__ int    g_cnt[B_ * NCELL];      // zeroed by agg (last kernel) for replay
__device__ int    g_cellStart[B_ * (NCELL + 1)];
__device__ int    g_rank[B_ * N_];        // intra-cell rank per point
__device__ float4 g_pts[B_ * N_];         // cell-sorted (x,y,z,sq)
__device__ int    g_pid[B_ * N_];         // original point index

// ---------------------------------------------------------------------------
// K1: W-fold block [0] + grid count blocks [1,129). Two-level count: local
// rank via shared atomics, one aggregated global atomicAdd per non-empty
// cell per block. Intra-cell order nondeterministic — covered by the
// order-invariant (d_bits, idx) selection key in knn.
// ---------------------------------------------------------------------------
__global__ __launch_bounds__(256) void k_prep(
    const float* __restrict__ coor,
    const float* __restrict__ W,
    const float* __restrict__ gamma_, const float* __restrict__ beta_,
    const float* __restrict__ rmean, const float* __restrict__ rvar)
{
    const int bid = blockIdx.x;
    const int tid = threadIdx.x;
    if (bid == 0) {
        if (tid < 64) {
            float sc = gamma_[tid] * rsqrtf(rvar[tid] + BN_EPS_);
            g_bias[tid] = beta_[tid] - rmean[tid] * sc;
            g_Wc[tid]       = W[tid * 67 + 64] * sc;
            g_Wc[64 + tid]  = W[tid * 67 + 65] * sc;
            g_Wc[128 + tid] = W[tid * 67 + 66] * sc;
        }
        for (int e = tid; e < 32 * 64; e += 256) {
            int c2 = e >> 6, d = e & 63;
            float sc = gamma_[d] * rsqrtf(rvar[d] + BN_EPS_);
            g_WsT2[e] = pack2(W[d * 67 + 2 * c2] * sc, W[d * 67 + 2 * c2 + 1] * sc);
        }
    } else {
        __shared__ int scnt[NCELL];
        __shared__ int sbase[NCELL];
        for (int i = tid; i < NCELL; i += 256) scnt[i] = 0;
        __syncthreads();

        const int id = (bid - 1) * 256 + tid;
        const int b = id / N_, n = id % N_;     // b uniform per block (32/batch)
        const float* cb = coor + b * 3 * N_;
        int cx = cell_clamp(cb[n]);
        int cy = cell_clamp(cb[N_ + n]);
        int cz = cell_clamp(cb[2 * N_ + n]);
        const int ci = (cz * NC + cy) * NC + cx;
        int lr = atomicAdd(&scnt[ci], 1);
        __syncthreads();

        for (int i = tid; i < NCELL; i += 256) {
            int c = scnt[i];
            if (c) sbase[i] = atomicAdd(&g_cnt[b * NCELL + i], c);
        }
        __syncthreads();
        g_rank[id] = sbase[ci] + lr;
    }
}

// ---------------------------------------------------------------------------
// K2: scatter only (128 blocks, atomic-free via local prefix scan).
// ---------------------------------------------------------------------------
__global__ __launch_bounds__(256) void scatter_kernel(const float* __restrict__ coor) {
    __shared__ int sPre[NCELL + 1];
    const int bid = blockIdx.x;
    const int tid = threadIdx.x;
    const int b  = bid >> 5;
    const int id = bid * 256 + tid;
    const int n  = id % N_;
    if (tid < 32) {
        int carry = 0;
        if (tid == 0) sPre[0] = 0;
        for (int c0 = 0; c0 < NCELL; c0 += 32) {
            int i = c0 + tid;
            int v = (i < NCELL) ? g_cnt[b * NCELL + i] : 0;
#pragma unroll
            for (int o = 1; o < 32; o <<= 1) {
                int tv = __shfl_up_sync(0xffffffffu, v, o);
                if (tid >= o) v += tv;
            }
            if (i < NCELL) sPre[i + 1] = carry + v;
            carry += __shfl_sync(0xffffffffu, v, 31);
        }
    }
    __syncthreads();
    for (int i = tid; i <= NCELL; i += 256)
        g_cellStart[b * (NCELL + 1) + i] = sPre[i];

    const float* cb = coor + b * 3 * N_;
    float x = cb[n], y = cb[N_ + n], z = cb[2 * N_ + n];
    float sq = fmaf(x, x, fmaf(y, y, z * z));   // same chain as query side
    int cx = cell_clamp(x), cy = cell_clamp(y), cz = cell_clamp(z);
    int pos = sPre[(cz * NC + cy) * NC + cx] + g_rank[id];
    g_pts[b * N_ + pos] = make_float4(x, y, z, sq);
    g_pid[b * N_ + pos] = n;
}

// ---------------------------------------------------------------------------
// K3 (block-fused): blocks [0,1024) = F GEMM, blocks [1024,5120) = KNN.
// CRITICAL vs R15: fused smem is only 8.4 KB (fgemm reads its 16 KB weight
// table via warp-uniform __ldg instead of staging it in shared), so resident
// knn blocks keep L1D ~160 KB — R15's regression was the 24.8 KB static smem
// shrinking L1D to ~30 KB and thrashing knn's g_pts working set.
// KNN algorithm is R11/R14 verbatim (order-invariant (d_bits,idx) heap,
// per-cell prune, nearest-cell-first, batched fill, provable early exit).
// ---------------------------------------------------------------------------
__global__ __launch_bounds__(256) void fgemm_knn(
    const float* __restrict__ coor, const float* __restrict__ fea)
{
    __shared__ __align__(16) char smem_buf[32 * 66 * 4];   // 8448 B union
    const int bid = blockIdx.x;
    const int tid = threadIdx.x;

    if (bid < 1024) {
        // ---- F GEMM: warp = 8 d's x 32 n's, 8 outputs/thread ----
        float* sfea = reinterpret_cast<float*>(smem_buf);   // [n][c] padded
        const int b   = bid >> 8;            // 256 n-chunks per batch
        const int n0  = (bid & 255) * 32;
        const int w   = tid >> 5, lane = tid & 31;

#pragma unroll
        for (int i = 0; i < 8; i++) {
            int c = w * 8 + i;
            sfea[lane * 66 + c] = fea[(b * 64 + c) * N_ + n0 + lane];
        }
        __syncthreads();

        const ull* frow = reinterpret_cast<const ull*>(sfea + lane * 66);
        const int d0 = w * 8;
        const ulonglong2* wt = reinterpret_cast<const ulonglong2*>(g_WsT2 + d0);
        ull acc[8];
#pragma unroll
        for (int j = 0; j < 8; j++) acc[j] = 0ull;
#pragma unroll 8
        for (int c2 = 0; c2 < 32; c2++) {
            ull f = frow[c2];
            // warp-uniform 16B loads from the 16 KB L1-resident table
            ulonglong2 w01 = __ldg(&wt[c2 * 32 + 0]);
            ulonglong2 w23 = __ldg(&wt[c2 * 32 + 1]);
            ulonglong2 w45 = __ldg(&wt[c2 * 32 + 2]);
            ulonglong2 w67 = __ldg(&wt[c2 * 32 + 3]);
            FMA2ACC(acc[0], f, w01.x); FMA2ACC(acc[1], f, w01.y);
            FMA2ACC(acc[2], f, w23.x); FMA2ACC(acc[3], f, w23.y);
            FMA2ACC(acc[4], f, w45.x); FMA2ACC(acc[5], f, w45.y);
            FMA2ACC(acc[6], f, w67.x); FMA2ACC(acc[7], f, w67.y);
        }
        float o[8];
#pragma unroll
        for (int j = 0; j < 8; j++) {
            float lo, hi; unpack2(acc[j], lo, hi);
            o[j] = lo + hi;
        }
        float4* dst = reinterpret_cast<float4*>(
            g_F + ((size_t)(b * N_ + n0 + lane)) * 64 + d0);
        dst[0] = make_float4(o[0], o[1], o[2], o[3]);
        dst[1] = make_float4(o[4], o[5], o[6], o[7]);
        return;
    }

    // ---- KNN ----
    ull (*s_stage)[32] = reinterpret_cast<ull(*)[32]>(smem_buf);
    const int kb   = bid - 1024;          // [0,4096)
    const int b    = kb >> 10;
    const int warp = tid >> 5;
    const int lane = tid & 31;
    const int q    = (kb & 1023) * 8 + warp;

    const float* cb = coor + b * 3 * N_;
    const float qx  = cb[q];
    const float qy  = cb[N_ + q];
    const float qz  = cb[2 * N_ + q];
    const float qsq = fmaf(qx, qx, fmaf(qy, qy, qz * qz));

    int s = 0, e = 0;
    unsigned mdu = INFB;
    {
        int qcx = cell_clamp(qx), qcy = cell_clamp(qy), qcz = cell_clamp(qz);
        if (lane < 27) {
            int cx = qcx + (lane % 3) - 1;
            int cy = qcy + ((lane / 3) % 3) - 1;
            int cz = qcz + (lane / 9) - 1;
            if (cx >= 0 && cx < NC && cy >= 0 && cy < NC && cz >= 0 && cz < NC) {
                float bx0 = cx * 0.2f, by0 = cy * 0.2f, bz0 = cz * 0.2f;
                float ddx = fmaxf(0.f, fmaxf(bx0 - qx, qx - (bx0 + 0.2f)));
                float ddy = fmaxf(0.f, fmaxf(by0 - qy, qy - (by0 + 0.2f)));
                float ddz = fmaxf(0.f, fmaxf(bz0 - qz, qz - (bz0 + 0.2f)));
                float md = ddx * ddx + ddy * ddy + ddz * ddz;
                if (md <= R2_ + 1e-5f) {
                    int ci = b * (NCELL + 1) + (cz * NC + cy) * NC + cx;
                    s = g_cellStart[ci];
                    e = g_cellStart[ci + 1];
                    mdu = __float_as_uint(md);
                }
            }
        }
    }

    unsigned mydb  = INFB;
    unsigned myidx = 0u;
    unsigned cmd = INFB, cmi = 0u;
    int maxlane = 0;
    int count = 0;

    const float4* pts = g_pts + b * N_;
    const int*    pid = g_pid + b * N_;

#pragma unroll 1
    for (int r = 0; r < 27; r++) {
        unsigned rmin = __reduce_min_sync(0xffffffffu, mdu);
        if (rmin == INFB) break;
        if (count == 32 &&
            __uint_as_float(cmd) + 4e-6f < __uint_as_float(rmin)) break;
        int j = __ffs(__ballot_sync(0xffffffffu, mdu == rmin)) - 1;
        int cs = __shfl_sync(0xffffffffu, s, j);
        int ce = __shfl_sync(0xffffffffu, e, j);
        if (lane == j) mdu = INFB;

        for (int i0 = cs; i0 < ce; i0 += 32) {
            int i = i0 + lane;
            bool act = i < ce;
            float4 p = act ? pts[i]
                           : make_float4(0.f, 0.f, 0.f, __int_as_float(0x7f800000));
            float dot = fmaf(qx, p.x, fmaf(qy, p.y, qz * p.z));
            float d   = fmaf(-2.f, dot, qsq + p.w);
            d = fmaxf(d, 0.f);
            unsigned db = __float_as_uint(d);
            unsigned pv = act ? (unsigned)pid[i] : 0u;
            bool ok = act && (d <= R2_) &&
                      (db < cmd || (db == cmd && pv < cmi));
            unsigned mask = __ballot_sync(0xffffffffu, ok);

            // ---- batched fill (heap not yet full) ----
            if (count < 32 && mask) {
                int m    = __popc(mask);
                int take = min(32 - count, m);
                int rank = __popc(mask & ((1u << lane) - 1u));
                if (ok && rank < take)
                    s_stage[warp][rank] = ((ull)db << 32) | pv;
                __syncwarp();
                int rr = lane - count;
                if (rr >= 0 && rr < take) {
                    ull v = s_stage[warp][rr];
                    mydb  = (unsigned)(v >> 32);
                    myidx = (unsigned)v;
                }
                count += take;
                if (take == m) mask = 0;
                else
                    for (int t = 0; t < take; t++) mask &= mask - 1;
                if (count == 32) {
                    cmd = __reduce_max_sync(0xffffffffu, mydb);
                    bool eq = (mydb == cmd);
                    cmi = __reduce_max_sync(0xffffffffu, eq ? myidx : 0u);
                    maxlane = __ffs(__ballot_sync(0xffffffffu,
                                        eq && (myidx == cmi))) - 1;
                }
            }

            // ---- eviction (heap full) ----
            while (mask) {
                int jj = __ffs(mask) - 1;
                mask &= mask - 1;
                unsigned djb = __shfl_sync(0xffffffffu, db, jj);
                unsigned cj  = __shfl_sync(0xffffffffu, pv, jj);
                if (djb < cmd || (djb == cmd && cj < cmi)) {
                    if (lane == maxlane) { mydb = djb; myidx = cj; }
                    cmd = __reduce_max_sync(0xffffffffu, mydb);
                    bool eq = (mydb == cmd);
                    cmi = __reduce_max_sync(0xffffffffu, eq ? myidx : 0u);
                    maxlane = __ffs(__ballot_sync(0xffffffffu,
                                        eq && (myidx == cmi))) - 1;
                }
            }
        }
    }
    int finalIdx = (__uint_as_float(mydb) <= R2_) ? (int)myidx : q;
    g_gidx[(b * N_ + q) * K_ + lane] = finalIdx;
}

// ---------------------------------------------------------------------------
// Aggregation: R14 verbatim — warp = one query (64 d's, 2 per lane, f32x2),
// index order, k-loop unroll 8. Block (0,0) re-zeroes g_cnt for replay.
// ---------------------------------------------------------------------------
__global__ __launch_bounds__(128) void agg_kernel(const float* __restrict__ coor,
                                                  float* __restrict__ out) {
    __shared__ __align__(16) float4 scc[4 * 32];
    __shared__ float sout[4 * 64];

    const int b    = blockIdx.y;
    const int q0   = blockIdx.x * 4;
    const int tid  = threadIdx.x;
    const int q    = tid >> 5;
    const int lane = tid & 31;
    const float* cb = coor + b * 3 * N_;

    if (blockIdx.x == 0 && b == 0)
        for (int i = tid; i < B_ * NCELL; i += 128) g_cnt[i] = 0;

    {
        int id = g_gidx[(b * N_ + q0 + q) * K_ + lane];
        scc[tid] = make_float4((cb[id] - cb[q0 + q]) * 5.0f,
                               (cb[N_ + id] - cb[N_ + q0 + q]) * 5.0f,
                               (cb[2 * N_ + id] - cb[2 * N_ + q0 + q]) * 5.0f,
                               __int_as_float(id));
    }
    __syncthreads();

    const ull wx2 = reinterpret_cast<const ull*>(g_Wc)[lane];
    const ull wy2 = reinterpret_cast<const ull*>(g_Wc + 64)[lane];
    const ull wz2 = reinterpret_cast<const ull*>(g_Wc + 128)[lane];
    const float2 bb = reinterpret_cast<const float2*>(g_bias)[lane];
    const float* Fb = g_F + (size_t)(b * N_) * 64;

    float m0 = __int_as_float(0xff800000), m1 = m0;
#pragma unroll 8
    for (int k = 0; k < 32; k++) {
        float4 cc = scc[q * 32 + k];
        int id = __float_as_int(cc.w);
        ull y = reinterpret_cast<const ull*>(Fb + id * 64)[lane];
        FMA2ACC(y, pack2(cc.x, cc.x), wx2);
        FMA2ACC(y, pack2(cc.y, cc.y), wy2);
        FMA2ACC(y, pack2(cc.z, cc.z), wz2);
        float y0, y1; unpack2(y, y0, y1);
        m0 = fmaxf(m0, y0);
        m1 = fmaxf(m1, y1);
    }
    sout[q * 64 + 2 * lane]     = fmaxf(m0 + bb.x, 0.f);
    sout[q * 64 + 2 * lane + 1] = fmaxf(m1 + bb.y, 0.f);
    __syncthreads();

    if (tid < 64) {
        float4 v = make_float4(sout[tid], sout[64 + tid],
                               sout[128 + tid], sout[192 + tid]);
        *reinterpret_cast<float4*>(&out[(b * 64 + tid) * N_ + q0]) = v;
    }
}

// ---------------------------------------------------------------------------
extern "C" void kernel_launch(void* const* d_in, const int* in_sizes, int n_in,
                              void* d_out, int out_size) {
    const float* coor  = (const float*)d_in[0];
    const float* fea   = (const float*)d_in[1];
    const float* W     = (const float*)d_in[2];
    const float* gamma = (const float*)d_in[3];
    const float* beta  = (const float*)d_in[4];
    const float* rmean = (const float*)d_in[5];
    const float* rvar  = (const float*)d_in[6];
    float* out = (float*)d_out;

    k_prep<<<1 + B_ * N_ / 256, 256>>>(coor, W, gamma, beta, rmean, rvar);
    scatter_kernel<<<128, 256>>>(coor);
    fgemm_knn<<<1024 + (N_ / 8) * B_, 256>>>(coor, fea);
    agg_kernel<<<dim3(N_ / 4, B_), 128>>>(coor, out);
}

// round 17
// speedup vs baseline: 1.0992x; 1.0992x over previous
#include <cuda_runtime.h>

#define B_ 4
#define C_ 64
#define N_ 8192
#define K_ 32
#define R2_ 0.04f
#define BN_EPS_ 1e-5f
#define NC 5
#define NCELL (NC * NC * NC)
#define CAP 160
#define OVCAP 2048
#define INFB 0x7f800000u

typedef unsigned long long ull;

#define FMA2ACC(acc, a, bb) asm("fma.rn.f32x2 %0, %1, %2, %0;" : "+l"(acc) : "l"(a), "l"(bb))

__device__ __forceinline__ ull pack2(float lo, float hi) {
    ull r; asm("mov.b64 %0, {%1, %2};" : "=l"(r) : "f"(lo), "f"(hi)); return r;
}
__device__ __forceinline__ void unpack2(ull v, float& lo, float& hi) {
    asm("mov.b64 {%0, %1}, %2;" : "=f"(lo), "=f"(hi) : "l"(v));
}
__device__ __forceinline__ int cell_clamp(float v) {
    int c = (int)(v * 5.0f);
    return min(NC - 1, max(0, c));
}

// Scratch (static __device__ arrays — no allocation)
__device__ float  g_F[B_ * N_ * C_];      // F[b][n][d] = fea row . W_fea[d] * scale
__device__ int    g_gidx[B_ * N_ * K_];   // final (masked) neighbor indices
__device__ __align__(16) ull g_WsT2[32 * 64];  // packed (w[2c],w[2c+1]) per d
__device__ float  g_Wc[3 * 64];           // coord weights * scale
__device__ float  g_bias[64];             // BN-folded bias
// grid structures (capacity binning — no scatter/scan stage)
__device__ int    g_cnt[B_ * NCELL];      // per-cell totals; zeroed by agg
__device__ int    g_ovf_cnt[B_];          // overflow counts;  zeroed by agg
__device__ float4 g_pts[B_ * NCELL * CAP];   // binned (x,y,z,sq)
__device__ int    g_pid[B_ * NCELL * CAP];   // original point index
__device__ float4 g_ovfp[B_ * OVCAP];     // overflow points (empty in practice)
__device__ int    g_ovfi[B_ * OVCAP];

// ---------------------------------------------------------------------------
// K1: block 0 = BN fold into W; blocks [1,129) = two-level capacity binning.
// Local rank via shared atomics + one aggregated global atomicAdd per
// non-empty cell per block; points land directly at cell*CAP + rank.
// rank >= CAP (never on this data; cells avg 65) goes to the overflow list,
// which knn scans through the same order-invariant insert path.
// ---------------------------------------------------------------------------
__global__ __launch_bounds__(256) void k_prep(
    const float* __restrict__ coor,
    const float* __restrict__ W,
    const float* __restrict__ gamma_, const float* __restrict__ beta_,
    const float* __restrict__ rmean, const float* __restrict__ rvar)
{
    const int bid = blockIdx.x;
    const int tid = threadIdx.x;
    if (bid == 0) {
        if (tid < 64) {
            float sc = gamma_[tid] * rsqrtf(rvar[tid] + BN_EPS_);
            g_bias[tid] = beta_[tid] - rmean[tid] * sc;
            g_Wc[tid]       = W[tid * 67 + 64] * sc;
            g_Wc[64 + tid]  = W[tid * 67 + 65] * sc;
            g_Wc[128 + tid] = W[tid * 67 + 66] * sc;
        }
        for (int e = tid; e < 32 * 64; e += 256) {
            int c2 = e >> 6, d = e & 63;
            float sc = gamma_[d] * rsqrtf(rvar[d] + BN_EPS_);
            g_WsT2[e] = pack2(W[d * 67 + 2 * c2] * sc, W[d * 67 + 2 * c2 + 1] * sc);
        }
    } else {
        __shared__ int scnt[NCELL];
        __shared__ int sbase[NCELL];
        for (int i = tid; i < NCELL; i += 256) scnt[i] = 0;
        __syncthreads();

        const int id = (bid - 1) * 256 + tid;
        const int b = id / N_, n = id % N_;     // b uniform per block (32/batch)
        const float* cb = coor + b * 3 * N_;
        float x = cb[n], y = cb[N_ + n], z = cb[2 * N_ + n];
        float sq = fmaf(x, x, fmaf(y, y, z * z));   // same chain as query side
        int cx = cell_clamp(x), cy = cell_clamp(y), cz = cell_clamp(z);
        const int ci = (cz * NC + cy) * NC + cx;
        int lr = atomicAdd(&scnt[ci], 1);
        __syncthreads();

        for (int i = tid; i < NCELL; i += 256) {
            int c = scnt[i];
            if (c) sbase[i] = atomicAdd(&g_cnt[b * NCELL + i], c);
        }
        __syncthreads();

        int slot = sbase[ci] + lr;
        if (slot < CAP) {
            int gp = (b * NCELL + ci) * CAP + slot;
            g_pts[gp] = make_float4(x, y, z, sq);
            g_pid[gp] = n;
        } else {
            int o = atomicAdd(&g_ovf_cnt[b], 1);
            g_ovfp[b * OVCAP + o] = make_float4(x, y, z, sq);
            g_ovfi[b * OVCAP + o] = n;
        }
    }
}

// ---------------------------------------------------------------------------
// K2: F GEMM (R14 verbatim): warp = 8 d's x 32 n's, 8 outputs/thread,
// weights staged coalesced from g_WsT2 into shared.
// ---------------------------------------------------------------------------
__global__ __launch_bounds__(256) void fgemm_kernel(const float* __restrict__ fea) {
    __shared__ ull s_wt[32 * 64];                       // [c2][d]  16 KB
    __shared__ __align__(16) float sfea[32 * 66];       // [n][c] padded
    const int bid = blockIdx.x;
    const int tid = threadIdx.x;
    const int b   = bid >> 8;            // 256 n-chunks per batch
    const int n0  = (bid & 255) * 32;
    const int w   = tid >> 5, lane = tid & 31;

    for (int e = tid; e < 32 * 64; e += 256) s_wt[e] = g_WsT2[e];
#pragma unroll
    for (int i = 0; i < 8; i++) {
        int c = w * 8 + i;
        sfea[lane * 66 + c] = fea[(b * 64 + c) * N_ + n0 + lane];
    }
    __syncthreads();

    const ull* frow = reinterpret_cast<const ull*>(sfea + lane * 66);
    const int d0 = w * 8;
    ull acc[8];
#pragma unroll
    for (int j = 0; j < 8; j++) acc[j] = 0ull;
#pragma unroll 8
    for (int c2 = 0; c2 < 32; c2++) {
        ull f = frow[c2];
        const ull* wr = s_wt + c2 * 64 + d0;
        ulonglong2 w01 = *reinterpret_cast<const ulonglong2*>(wr);
        ulonglong2 w23 = *reinterpret_cast<const ulonglong2*>(wr + 2);
        ulonglong2 w45 = *reinterpret_cast<const ulonglong2*>(wr + 4);
        ulonglong2 w67 = *reinterpret_cast<const ulonglong2*>(wr + 6);
        FMA2ACC(acc[0], f, w01.x); FMA2ACC(acc[1], f, w01.y);
        FMA2ACC(acc[2], f, w23.x); FMA2ACC(acc[3], f, w23.y);
        FMA2ACC(acc[4], f, w45.x); FMA2ACC(acc[5], f, w45.y);
        FMA2ACC(acc[6], f, w67.x); FMA2ACC(acc[7], f, w67.y);
    }
    float o[8];
#pragma unroll
    for (int j = 0; j < 8; j++) {
        float lo, hi; unpack2(acc[j], lo, hi);
        o[j] = lo + hi;
    }
    float4* dst = reinterpret_cast<float4*>(
        g_F + ((size_t)(b * N_ + n0 + lane)) * 64 + d0);
    dst[0] = make_float4(o[0], o[1], o[2], o[3]);
    dst[1] = make_float4(o[4], o[5], o[6], o[7]);
}

// ---------------------------------------------------------------------------
// KNN insert machinery (shared by cell ranges and the overflow list).
// Order-invariant selection key (d_bits, idx); batched fill; eviction loop.
// Must be called warp-convergent.
// ---------------------------------------------------------------------------
struct KnnState {
    unsigned mydb, myidx, cmd, cmi;
    int maxlane, count;
};

__device__ __forceinline__ void scan_range(
    const float4* __restrict__ pts, const int* __restrict__ pid,
    int cs, int ce,
    float qx, float qy, float qz, float qsq,
    int lane, ull* stage, KnnState& st)
{
    for (int i0 = cs; i0 < ce; i0 += 32) {
        int i = i0 + lane;
        bool act = i < ce;
        float4 p = act ? pts[i]
                       : make_float4(0.f, 0.f, 0.f, __int_as_float(0x7f800000));
        float dot = fmaf(qx, p.x, fmaf(qy, p.y, qz * p.z));
        float d   = fmaf(-2.f, dot, qsq + p.w);
        d = fmaxf(d, 0.f);   // keep float-as-uint compare monotonic
        unsigned db = __float_as_uint(d);
        unsigned pv = act ? (unsigned)pid[i] : 0u;
        bool ok = act && (d <= R2_) &&
                  (db < st.cmd || (db == st.cmd && pv < st.cmi));
        unsigned mask = __ballot_sync(0xffffffffu, ok);

        // ---- batched fill (heap not yet full) ----
        if (st.count < 32 && mask) {
            int m    = __popc(mask);
            int take = min(32 - st.count, m);
            int rank = __popc(mask & ((1u << lane) - 1u));
            if (ok && rank < take)
                stage[rank] = ((ull)db << 32) | pv;
            __syncwarp();
            int rr = lane - st.count;
            if (rr >= 0 && rr < take) {
                ull v = stage[rr];
                st.mydb  = (unsigned)(v >> 32);
                st.myidx = (unsigned)v;
            }
            st.count += take;
            if (take == m) mask = 0;
            else
                for (int t = 0; t < take; t++) mask &= mask - 1;
            if (st.count == 32) {
                st.cmd = __reduce_max_sync(0xffffffffu, st.mydb);
                bool eq = (st.mydb == st.cmd);
                st.cmi = __reduce_max_sync(0xffffffffu, eq ? st.myidx : 0u);
                st.maxlane = __ffs(__ballot_sync(0xffffffffu,
                                    eq && (st.myidx == st.cmi))) - 1;
            }
        }

        // ---- eviction (heap full) ----
        while (mask) {
            int jj = __ffs(mask) - 1;
            mask &= mask - 1;
            unsigned djb = __shfl_sync(0xffffffffu, db, jj);
            unsigned cj  = __shfl_sync(0xffffffffu, pv, jj);
            if (djb < st.cmd || (djb == st.cmd && cj < st.cmi)) {
                if (lane == st.maxlane) { st.mydb = djb; st.myidx = cj; }
                st.cmd = __reduce_max_sync(0xffffffffu, st.mydb);
                bool eq = (st.mydb == st.cmd);
                st.cmi = __reduce_max_sync(0xffffffffu, eq ? st.myidx : 0u);
                st.maxlane = __ffs(__ballot_sync(0xffffffffu,
                                    eq && (st.myidx == st.cmi))) - 1;
            }
        }
    }
}

// ---------------------------------------------------------------------------
// K3: KNN — R14 algorithm (per-cell prune, nearest-cell-first, provable
// early exit). Cell ranges come from g_cnt/CAP; the (normally empty)
// overflow list is pre-scanned through the same insert path.
// ---------------------------------------------------------------------------
__global__ __launch_bounds__(256) void knn_kernel(const float* __restrict__ coor) {
    __shared__ ull s_stage[8][32];

    const int b    = blockIdx.y;
    const int warp = threadIdx.x >> 5;
    const int lane = threadIdx.x & 31;
    const int q    = blockIdx.x * 8 + warp;

    const float* cb = coor + b * 3 * N_;
    const float qx  = cb[q];
    const float qy  = cb[N_ + q];
    const float qz  = cb[2 * N_ + q];
    const float qsq = fmaf(qx, qx, fmaf(qy, qy, qz * qz));

    int s = 0, e = 0;
    unsigned mdu = INFB;
    {
        int qcx = cell_clamp(qx), qcy = cell_clamp(qy), qcz = cell_clamp(qz);
        if (lane < 27) {
            int cx = qcx + (lane % 3) - 1;
            int cy = qcy + ((lane / 3) % 3) - 1;
            int cz = qcz + (lane / 9) - 1;
            if (cx >= 0 && cx < NC && cy >= 0 && cy < NC && cz >= 0 && cz < NC) {
                float bx0 = cx * 0.2f, by0 = cy * 0.2f, bz0 = cz * 0.2f;
                float ddx = fmaxf(0.f, fmaxf(bx0 - qx, qx - (bx0 + 0.2f)));
                float ddy = fmaxf(0.f, fmaxf(by0 - qy, qy - (by0 + 0.2f)));
                float ddz = fmaxf(0.f, fmaxf(bz0 - qz, qz - (bz0 + 0.2f)));
                float md = ddx * ddx + ddy * ddy + ddz * ddz;
                if (md <= R2_ + 1e-5f) {
                    int ci = b * NCELL + (cz * NC + cy) * NC + cx;
                    s = ci * CAP;
                    e = s + min(g_cnt[ci], CAP);
                    mdu = __float_as_uint(md);
                }
            }
        }
    }

    KnnState st;
    st.mydb = INFB; st.myidx = 0u;
    st.cmd = INFB;  st.cmi = 0u;
    st.maxlane = 0; st.count = 0;

    // overflow pre-scan (empty on this data; kept for correctness)
    {
        int novf = g_ovf_cnt[b];
        if (novf > 0)
            scan_range(g_ovfp + b * OVCAP, g_ovfi + b * OVCAP, 0, novf,
                       qx, qy, qz, qsq, lane, s_stage[warp], st);
    }

#pragma unroll 1
    for (int r = 0; r < 27; r++) {
        unsigned rmin = __reduce_min_sync(0xffffffffu, mdu);
        if (rmin == INFB) break;
        if (st.count == 32 &&
            __uint_as_float(st.cmd) + 4e-6f < __uint_as_float(rmin)) break;
        int j = __ffs(__ballot_sync(0xffffffffu, mdu == rmin)) - 1;
        int cs = __shfl_sync(0xffffffffu, s, j);
        int ce = __shfl_sync(0xffffffffu, e, j);
        if (lane == j) mdu = INFB;

        scan_range(g_pts, g_pid, cs, ce, qx, qy, qz, qsq,
                   lane, s_stage[warp], st);
    }
    int finalIdx = (__uint_as_float(st.mydb) <= R2_) ? (int)st.myidx : q;
    g_gidx[(b * N_ + q) * K_ + lane] = finalIdx;
}

// ---------------------------------------------------------------------------
// K4: Aggregation — warp = one query (64 d's, 2 per lane via f32x2), 8
// queries per 256-thread block, k-loop unroll 8 (R14 math verbatim).
// Block (0,0) re-zeroes g_cnt and g_ovf_cnt for the next graph replay.
// ---------------------------------------------------------------------------
__global__ __launch_bounds__(256) void agg_kernel(const float* __restrict__ coor,
                                                  float* __restrict__ out) {
    __shared__ __align__(16) float4 scc[8 * 32];
    __shared__ float sout[8 * 64];

    const int b    = blockIdx.y;
    const int q0   = blockIdx.x * 8;
    const int tid  = threadIdx.x;
    const int q    = tid >> 5;
    const int lane = tid & 31;
    const float* cb = coor + b * 3 * N_;

    if (blockIdx.x == 0 && b == 0) {
        for (int i = tid; i < B_ * NCELL; i += 256) g_cnt[i] = 0;
        if (tid < B_) g_ovf_cnt[tid] = 0;
    }

    {
        int id = g_gidx[(b * N_ + q0 + q) * K_ + lane];
        scc[tid] = make_float4((cb[id] - cb[q0 + q]) * 5.0f,
                               (cb[N_ + id] - cb[N_ + q0 + q]) * 5.0f,
                               (cb[2 * N_ + id] - cb[2 * N_ + q0 + q]) * 5.0f,
                               __int_as_float(id));
    }
    __syncthreads();

    const ull wx2 = reinterpret_cast<const ull*>(g_Wc)[lane];
    const ull wy2 = reinterpret_cast<const ull*>(g_Wc + 64)[lane];
    const ull wz2 = reinterpret_cast<const ull*>(g_Wc + 128)[lane];
    const float2 bb = reinterpret_cast<const float2*>(g_bias)[lane];
    const float* Fb = g_F + (size_t)(b * N_) * 64;

    float m0 = __int_as_float(0xff800000), m1 = m0;
#pragma unroll 8
    for (int k = 0; k < 32; k++) {
        float4 cc = scc[q * 32 + k];
        int id = __float_as_int(cc.w);
        ull y = reinterpret_cast<const ull*>(Fb + id * 64)[lane];
        FMA2ACC(y, pack2(cc.x, cc.x), wx2);
        FMA2ACC(y, pack2(cc.y, cc.y), wy2);
        FMA2ACC(y, pack2(cc.z, cc.z), wz2);
        float y0, y1; unpack2(y, y0, y1);
        m0 = fmaxf(m0, y0);
        m1 = fmaxf(m1, y1);
    }
    sout[q * 64 + 2 * lane]     = fmaxf(m0 + bb.x, 0.f);
    sout[q * 64 + 2 * lane + 1] = fmaxf(m1 + bb.y, 0.f);
    __syncthreads();

    {   // transposed store: thread -> d-row (tid>>2), query pair (tid&3)*2
        int d = tid >> 2, qp = (tid & 3) * 2;
        float2 v = make_float2(sout[qp * 64 + d], sout[(qp + 1) * 64 + d]);
        *reinterpret_cast<float2*>(&out[(b * 64 + d) * N_ + q0 + qp]) = v;
    }
}

// ---------------------------------------------------------------------------
extern "C" void kernel_launch(void* const* d_in, const int* in_sizes, int n_in,
                              void* d_out, int out_size) {
    const float* coor  = (const float*)d_in[0];
    const float* fea   = (const float*)d_in[1];
    const float* W     = (const float*)d_in[2];
    const float* gamma = (const float*)d_in[3];
    const float* beta  = (const float*)d_in[4];
    const float* rmean = (const float*)d_in[5];
    const float* rvar  = (const float*)d_in[6];
    float* out = (float*)d_out;

    k_prep<<<1 + B_ * N_ / 256, 256>>>(coor, W, gamma, beta, rmean, rvar);
    fgemm_kernel<<<(N_ / 32) * B_, 256>>>(fea);
    knn_kernel<<<dim3(N_ / 8, B_), 256>>>(coor);
    agg_kernel<<<dim3(N_ / 8, B_), 256>>>(coor, out);
}